// round 1
// baseline (speedup 1.0000x reference)
#include <cuda_runtime.h>

// Problem constants (fixed by the dataset)
#define BN      131072      // B*N = 256*512
#define TT      12          // T
#define FF      2
#define HH      64
#define G3      192         // 3*H
#define CC      10
#define TOUT    12
#define PITCH   196         // padded shared row pitch for w_hh^T (k-major)

#define NTHREADS 384

// ---- shared layout (floats) ----
#define OFF_WE    0                    // enc w_hh^T  [k*196+g], 64*196
#define OFF_WD    12544                // dec w_hh^T
#define OFF_WAE   25088                // enc w_ih feature0 [192]
#define OFF_WBE   25280                // enc w_ih feature1
#define OFF_WAD   25472                // dec w_ih [192]
#define OFF_WBD   25664                // zeros
#define OFF_BIHE  25856
#define OFF_BHHE  26048
#define OFF_BIHD  26240
#define OFF_BHHD  26432
#define OFF_L1W   26624                // [64]
#define OFF_L1B   26688                // [1]
#define OFF_W2    26692                // [144]
#define OFF_B2    26836                // [12]
#define OFF_HS    26848                // per-thread h mirror [384*65]
#define SMEM_FLOATS (26848 + NTHREADS*65)
#define SMEM_BYTES  (SMEM_FLOATS*4)

// packed f32x2 FMA (sm_103a FFMA2)
#define FMA2(acc, a, b) asm("fma.rn.f32x2 %0, %1, %2, %0;" : "+l"(acc) : "l"(a), "l"(b))

__device__ __forceinline__ unsigned long long pack2(float lo, float hi) {
    unsigned long long v;
    asm("mov.b64 %0, {%1, %2};" : "=l"(v) : "f"(lo), "f"(hi));
    return v;
}
__device__ __forceinline__ float2 unpack2(unsigned long long v) {
    float2 r;
    asm("mov.b64 {%0, %1}, %2;" : "=f"(r.x), "=f"(r.y) : "l"(v));
    return r;
}

__device__ __forceinline__ float sigmoidf_(float x) {
    return __fdividef(1.0f, 1.0f + __expf(-x));
}
__device__ __forceinline__ float tanhf_(float x) {
    return __fdividef(2.0f, 1.0f + __expf(-2.0f * x)) - 1.0f;
}

// device-global scratch for per-channel decoder outputs: [c][o][seq]
__device__ float g_vals[(size_t)CC * TOUT * BN];

// One GRU step. h in registers; hs = per-thread shared mirror (65-float pitch).
// whh: shared, k-major [k*PITCH + g]. wA/wB: per-feature input weights (192 each).
__device__ __forceinline__ void gru_step(
    float (&h)[HH], float* hs,
    const float* __restrict__ whh,
    const float* __restrict__ wA, const float* __restrict__ wB,
    const float* __restrict__ bih, const float* __restrict__ bhh,
    float x0, float x1)
{
    // mirror old h into shared (needed for runtime-indexed old-h read in epilogue)
    #pragma unroll
    for (int k = 0; k < HH; ++k) hs[k] = h[k];

    for (int j = 0; j < HH; j += 8) {
        unsigned long long aR[4], aZ[4], aN[4];
        // init accumulators: gx(+b_ih) + b_hh for r,z ; b_hh only for n
        #pragma unroll
        for (int p = 0; p < 4; ++p) {
            int g0 = j + 2 * p, g1 = g0 + 1;
            float r0 = fmaf(wA[g0], x0, fmaf(wB[g0], x1, bih[g0] + bhh[g0]));
            float r1 = fmaf(wA[g1], x0, fmaf(wB[g1], x1, bih[g1] + bhh[g1]));
            float z0 = fmaf(wA[64 + g0], x0, fmaf(wB[64 + g0], x1, bih[64 + g0] + bhh[64 + g0]));
            float z1 = fmaf(wA[64 + g1], x0, fmaf(wB[64 + g1], x1, bih[64 + g1] + bhh[64 + g1]));
            aR[p] = pack2(r0, r1);
            aZ[p] = pack2(z0, z1);
            aN[p] = pack2(bhh[128 + g0], bhh[128 + g1]);
        }
        const float* wbase = whh + j;
        #pragma unroll
        for (int k = 0; k < HH; ++k) {
            unsigned long long hk2;
            asm("mov.b64 %0, {%1, %1};" : "=l"(hk2) : "f"(h[k]));
            const ulonglong2* pr = (const ulonglong2*)(wbase + k * PITCH);
            const ulonglong2* pz = (const ulonglong2*)(wbase + k * PITCH + 64);
            const ulonglong2* pn = (const ulonglong2*)(wbase + k * PITCH + 128);
            ulonglong2 r0 = pr[0], r1 = pr[1];
            ulonglong2 z0 = pz[0], z1 = pz[1];
            ulonglong2 n0 = pn[0], n1 = pn[1];
            FMA2(aR[0], hk2, r0.x); FMA2(aR[1], hk2, r0.y);
            FMA2(aR[2], hk2, r1.x); FMA2(aR[3], hk2, r1.y);
            FMA2(aZ[0], hk2, z0.x); FMA2(aZ[1], hk2, z0.y);
            FMA2(aZ[2], hk2, z1.x); FMA2(aZ[3], hk2, z1.y);
            FMA2(aN[0], hk2, n0.x); FMA2(aN[1], hk2, n0.y);
            FMA2(aN[2], hk2, n1.x); FMA2(aN[3], hk2, n1.y);
        }
        // epilogue for 8 gates
        #pragma unroll
        for (int p = 0; p < 4; ++p) {
            float2 rv = unpack2(aR[p]);
            float2 zv = unpack2(aZ[p]);
            float2 nv = unpack2(aN[p]);
            #pragma unroll
            for (int u = 0; u < 2; ++u) {
                int g = j + 2 * p + u;
                float rr = sigmoidf_(u ? rv.y : rv.x);
                float zz = sigmoidf_(u ? zv.y : zv.x);
                float ghn = u ? nv.y : nv.x;
                float gxn = fmaf(wA[128 + g], x0, fmaf(wB[128 + g], x1, bih[128 + g]));
                float nn = tanhf_(fmaf(rr, ghn, gxn));
                float hold = hs[g];
                hs[g] = nn + zz * (hold - nn);
            }
        }
    }
    // read updated h back to registers
    #pragma unroll
    for (int k = 0; k < HH; ++k) h[k] = hs[k];
}

__global__ void __launch_bounds__(NTHREADS, 1) krnn_main(
    const float* __restrict__ X,
    const float* __restrict__ enc_w_ih, const float* __restrict__ enc_w_hh,
    const float* __restrict__ enc_b_ih, const float* __restrict__ enc_b_hh,
    const float* __restrict__ dec_w_ih, const float* __restrict__ dec_w_hh,
    const float* __restrict__ dec_b_ih, const float* __restrict__ dec_b_hh,
    const float* __restrict__ lin1_w,  const float* __restrict__ lin1_b,
    const float* __restrict__ lin2_w,  const float* __restrict__ lin2_b)
{
    extern __shared__ float sm[];
    const int c   = blockIdx.y;
    const int tid = threadIdx.x;

    // ---- cooperative weight staging ----
    {
        const float* ew = enc_w_hh + c * (G3 * HH);
        const float* dw = dec_w_hh + c * (G3 * HH);
        for (int idx = tid; idx < G3 * HH; idx += NTHREADS) {
            int g = idx >> 6, k = idx & 63;          // global is [g][k], coalesced read
            sm[OFF_WE + k * PITCH + g] = ew[idx];
            sm[OFF_WD + k * PITCH + g] = dw[idx];
        }
        const float* ewi = enc_w_ih + c * (G3 * FF);
        const float* dwi = dec_w_ih + c * G3;
        for (int idx = tid; idx < G3; idx += NTHREADS) {
            sm[OFF_WAE + idx] = ewi[2 * idx];
            sm[OFF_WBE + idx] = ewi[2 * idx + 1];
            sm[OFF_WAD + idx] = dwi[idx];
            sm[OFF_WBD + idx] = 0.0f;
            sm[OFF_BIHE + idx] = enc_b_ih[c * G3 + idx];
            sm[OFF_BHHE + idx] = enc_b_hh[c * G3 + idx];
            sm[OFF_BIHD + idx] = dec_b_ih[c * G3 + idx];
            sm[OFF_BHHD + idx] = dec_b_hh[c * G3 + idx];
        }
        if (tid < HH)  sm[OFF_L1W + tid] = lin1_w[c * HH + tid];
        if (tid == 0)  sm[OFF_L1B] = lin1_b[c];
        if (tid < 144) sm[OFF_W2 + tid] = lin2_w[c * 144 + tid];
        if (tid < 12)  sm[OFF_B2 + tid] = lin2_b[c * 12 + tid];
    }
    __syncthreads();

    const int seq = blockIdx.x * NTHREADS + tid;
    if (seq >= BN) return;

    float* hs = sm + OFF_HS + tid * 65;

    // load this sequence's X row: 12x2 floats
    float Xl[24];
    {
        const float4* xp = (const float4*)(X + (size_t)seq * (TT * FF));
        #pragma unroll
        for (int q = 0; q < 6; ++q) {
            float4 v = xp[q];
            Xl[4 * q + 0] = v.x; Xl[4 * q + 1] = v.y;
            Xl[4 * q + 2] = v.z; Xl[4 * q + 3] = v.w;
        }
    }

    float h[HH];
    #pragma unroll
    for (int k = 0; k < HH; ++k) h[k] = 0.0f;

    // ---- encoder: s = c + 3 steps ----
    const int s = c + 3;
    const float* W2s = sm + OFF_W2;
    const float* B2s = sm + OFF_B2;
    for (int st = 0; st < s; ++st) {
        float x0 = B2s[st], x1 = B2s[st];
        #pragma unroll
        for (int t = 0; t < TT; ++t) {
            float w = W2s[st * TT + t];
            x0 = fmaf(Xl[2 * t],     w, x0);
            x1 = fmaf(Xl[2 * t + 1], w, x1);
        }
        gru_step(h, hs, sm + OFF_WE, sm + OFF_WAE, sm + OFF_WBE,
                 sm + OFF_BIHE, sm + OFF_BHHE, x0, x1);
    }

    // ---- decoder: 12 steps, scalar feedback ----
    float lv = Xl[22];   // X[seq, t=11, f=0]
    const float* L1W = sm + OFF_L1W;
    const float  l1b = sm[OFF_L1B];
    for (int st = 0; st < TOUT; ++st) {
        gru_step(h, hs, sm + OFF_WD, sm + OFF_WAD, sm + OFF_WBD,
                 sm + OFF_BIHD, sm + OFF_BHHD, lv, 0.0f);
        float v = l1b;
        #pragma unroll
        for (int k = 0; k < HH; ++k) v = fmaf(h[k], L1W[k], v);
        g_vals[((size_t)c * TOUT + st) * BN + seq] = v;
        lv = v;
    }
}

__global__ void __launch_bounds__(256) krnn_combine(
    const float* __restrict__ X,
    const float* __restrict__ embed1,
    float* __restrict__ out)
{
    const int seq = blockIdx.x * 256 + threadIdx.x;
    if (seq >= BN) return;

    float q[TT];
    #pragma unroll
    for (int t = 0; t < TT; ++t) q[t] = X[(size_t)seq * (TT * FF) + t * FF];

    float wq[TOUT];
    #pragma unroll
    for (int o = 0; o < TOUT; ++o) {
        float a = 0.0f;
        #pragma unroll
        for (int t = 0; t < TT; ++t) a = fmaf(q[t], embed1[t * TOUT + o], a);
        wq[o] = a;
    }

    float ov[TOUT * CC];
    #pragma unroll
    for (int cc = 0; cc < CC; ++cc)
        #pragma unroll
        for (int o = 0; o < TOUT; ++o)
            ov[o * CC + cc] = g_vals[((size_t)cc * TOUT + o) * BN + seq];

    float wc[CC];
    #pragma unroll
    for (int cc = 0; cc < CC; ++cc) {
        float a = 0.0f;
        #pragma unroll
        for (int o = 0; o < TOUT; ++o) a = fmaf(wq[o], ov[o * CC + cc], a);
        wc[cc] = a;
    }

    float m = wc[0];
    #pragma unroll
    for (int cc = 1; cc < CC; ++cc) m = fmaxf(m, wc[cc]);
    float e[CC]; float ssum = 0.0f;
    #pragma unroll
    for (int cc = 0; cc < CC; ++cc) { e[cc] = expf(wc[cc] - m); ssum += e[cc]; }
    float inv = 1.0f / ssum;

    #pragma unroll
    for (int o = 0; o < TOUT; ++o) {
        float a = 0.0f;
        #pragma unroll
        for (int cc = 0; cc < CC; ++cc) a = fmaf(ov[o * CC + cc], e[cc], a);
        out[(size_t)seq * TOUT + o] = a * inv;
    }
}

extern "C" void kernel_launch(void* const* d_in, const int* in_sizes, int n_in,
                              void* d_out, int out_size)
{
    // input order: A, X, enc_w_ih, enc_w_hh, enc_b_ih, enc_b_hh,
    //              dec_w_ih, dec_w_hh, dec_b_ih, dec_b_hh,
    //              lin1_w, lin1_b, lin2_w, lin2_b, embed1
    const float* X        = (const float*)d_in[1];
    const float* enc_w_ih = (const float*)d_in[2];
    const float* enc_w_hh = (const float*)d_in[3];
    const float* enc_b_ih = (const float*)d_in[4];
    const float* enc_b_hh = (const float*)d_in[5];
    const float* dec_w_ih = (const float*)d_in[6];
    const float* dec_w_hh = (const float*)d_in[7];
    const float* dec_b_ih = (const float*)d_in[8];
    const float* dec_b_hh = (const float*)d_in[9];
    const float* lin1_w   = (const float*)d_in[10];
    const float* lin1_b   = (const float*)d_in[11];
    const float* lin2_w   = (const float*)d_in[12];
    const float* lin2_b   = (const float*)d_in[13];
    const float* embed1   = (const float*)d_in[14];

    cudaFuncSetAttribute(krnn_main, cudaFuncAttributeMaxDynamicSharedMemorySize, SMEM_BYTES);

    dim3 grid((BN + NTHREADS - 1) / NTHREADS, CC);
    krnn_main<<<grid, NTHREADS, SMEM_BYTES>>>(
        X, enc_w_ih, enc_w_hh, enc_b_ih, enc_b_hh,
        dec_w_ih, dec_w_hh, dec_b_ih, dec_b_hh,
        lin1_w, lin1_b, lin2_w, lin2_b);

    krnn_combine<<<BN / 256, 256>>>(X, embed1, (float*)d_out);
}

// round 2
// speedup vs baseline: 1.4283x; 1.4283x over previous
#include <cuda_runtime.h>

// Problem constants (fixed by the dataset)
#define BN    131072            // B*N
#define TT    12
#define HH    64
#define G3    192               // 3*H
#define CC    10
#define TOUT  12
#define NT    256               // threads per block (main kernel)

// ---- shared layout (floats) ----
#define OFF_W    0              // whh^T staged k-major [k*192 + g], 12288 floats
#define OFF_WA   12288          // w_ih feature0 [192]
#define OFF_WB   12480          // w_ih feature1 [192]
#define OFF_BIH  12672          // [192]
#define OFF_BHH  12864          // [192]
#define OFF_L1W  13056          // [64]
#define OFF_L1B  13120          // [1]
#define OFF_HS   13124          // h mirror: float2[64][NT]
#define SMEM_FLOATS (OFF_HS + HH*NT*2)
#define SMEM_BYTES  (SMEM_FLOATS*4)

// device-global scratch
__device__ float g_hv[(size_t)CC * TOUT * BN * 2];   // encoder inputs (x0,x1) pairs
__device__ float g_vals[(size_t)CC * TOUT * BN];     // decoder outputs

// packed f32x2 FMA (sm_103a FFMA2)
#define FMA2(acc, a, b) asm("fma.rn.f32x2 %0, %1, %2, %0;" : "+l"(acc) : "l"(a), "l"(b))

__device__ __forceinline__ unsigned long long pack2(float lo, float hi) {
    unsigned long long v;
    asm("mov.b64 %0, {%1, %2};" : "=l"(v) : "f"(lo), "f"(hi));
    return v;
}
__device__ __forceinline__ unsigned long long dup2(float x) {
    unsigned long long v;
    asm("mov.b64 %0, {%1, %1};" : "=l"(v) : "f"(x));
    return v;
}
__device__ __forceinline__ float2 unpack2(unsigned long long v) {
    float2 r;
    asm("mov.b64 {%0, %1}, %2;" : "=f"(r.x), "=f"(r.y) : "l"(v));
    return r;
}

__device__ __forceinline__ float sigmoidf_(float x) {
    return __fdividef(1.0f, 1.0f + __expf(-x));
}
__device__ __forceinline__ float tanhf_(float x) {
    return __fdividef(2.0f, 1.0f + __expf(-2.0f * x)) - 1.0f;
}

// One GRU step for TWO sequences (a,b) per thread.
// ha/hb: register-resident old h. hs (in smem): pairs {a,b} at [k*NT + tid];
// holds old h at entry (== registers), epilogue writes new h, reload at end.
template<bool HASX1>
__device__ __forceinline__ void gru_step2(
    float (&ha)[HH], float (&hb)[HH], float* sm, int tid,
    float xa0, float xa1, float xb0, float xb1)
{
    const float* whh = sm + OFF_W;
    float2* hs = (float2*)(sm + OFF_HS);

    #pragma unroll 1
    for (int j = 0; j < HH; j += 8) {
        // ---- stage per-block init coefficients (vectorized shared loads) ----
        float wAr[8], wAz[8], wBr[8], wBz[8], bR[8], bZ[8], bN[8];
        *(float4*)(wAr)     = *(const float4*)(sm + OFF_WA + j);
        *(float4*)(wAr + 4) = *(const float4*)(sm + OFF_WA + j + 4);
        *(float4*)(wAz)     = *(const float4*)(sm + OFF_WA + 64 + j);
        *(float4*)(wAz + 4) = *(const float4*)(sm + OFF_WA + 64 + j + 4);
        if (HASX1) {
            *(float4*)(wBr)     = *(const float4*)(sm + OFF_WB + j);
            *(float4*)(wBr + 4) = *(const float4*)(sm + OFF_WB + j + 4);
            *(float4*)(wBz)     = *(const float4*)(sm + OFF_WB + 64 + j);
            *(float4*)(wBz + 4) = *(const float4*)(sm + OFF_WB + 64 + j + 4);
        }
        {
            float4 i0 = *(const float4*)(sm + OFF_BIH + j);
            float4 i1 = *(const float4*)(sm + OFF_BIH + j + 4);
            float4 h0 = *(const float4*)(sm + OFF_BHH + j);
            float4 h1 = *(const float4*)(sm + OFF_BHH + j + 4);
            bR[0]=i0.x+h0.x; bR[1]=i0.y+h0.y; bR[2]=i0.z+h0.z; bR[3]=i0.w+h0.w;
            bR[4]=i1.x+h1.x; bR[5]=i1.y+h1.y; bR[6]=i1.z+h1.z; bR[7]=i1.w+h1.w;
            i0 = *(const float4*)(sm + OFF_BIH + 64 + j);
            i1 = *(const float4*)(sm + OFF_BIH + 64 + j + 4);
            h0 = *(const float4*)(sm + OFF_BHH + 64 + j);
            h1 = *(const float4*)(sm + OFF_BHH + 64 + j + 4);
            bZ[0]=i0.x+h0.x; bZ[1]=i0.y+h0.y; bZ[2]=i0.z+h0.z; bZ[3]=i0.w+h0.w;
            bZ[4]=i1.x+h1.x; bZ[5]=i1.y+h1.y; bZ[6]=i1.z+h1.z; bZ[7]=i1.w+h1.w;
            h0 = *(const float4*)(sm + OFF_BHH + 128 + j);
            h1 = *(const float4*)(sm + OFF_BHH + 128 + j + 4);
            bN[0]=h0.x; bN[1]=h0.y; bN[2]=h0.z; bN[3]=h0.w;
            bN[4]=h1.x; bN[5]=h1.y; bN[6]=h1.z; bN[7]=h1.w;
        }

        // ---- accumulator init: gx(r,z)+b_hh ; b_hh only for n ----
        unsigned long long aRa[4], aZa[4], aNa[4], aRb[4], aZb[4], aNb[4];
        #pragma unroll
        for (int p = 0; p < 4; ++p) {
            int g0 = 2 * p, g1 = g0 + 1;
            float ra0 = fmaf(wAr[g0], xa0, bR[g0]);
            float ra1 = fmaf(wAr[g1], xa0, bR[g1]);
            float za0 = fmaf(wAz[g0], xa0, bZ[g0]);
            float za1 = fmaf(wAz[g1], xa0, bZ[g1]);
            float rb0 = fmaf(wAr[g0], xb0, bR[g0]);
            float rb1 = fmaf(wAr[g1], xb0, bR[g1]);
            float zb0 = fmaf(wAz[g0], xb0, bZ[g0]);
            float zb1 = fmaf(wAz[g1], xb0, bZ[g1]);
            if (HASX1) {
                ra0 = fmaf(wBr[g0], xa1, ra0); ra1 = fmaf(wBr[g1], xa1, ra1);
                za0 = fmaf(wBz[g0], xa1, za0); za1 = fmaf(wBz[g1], xa1, za1);
                rb0 = fmaf(wBr[g0], xb1, rb0); rb1 = fmaf(wBr[g1], xb1, rb1);
                zb0 = fmaf(wBz[g0], xb1, zb0); zb1 = fmaf(wBz[g1], xb1, zb1);
            }
            aRa[p] = pack2(ra0, ra1); aZa[p] = pack2(za0, za1);
            aRb[p] = pack2(rb0, rb1); aZb[p] = pack2(zb0, zb1);
            aNa[p] = pack2(bN[g0], bN[g1]);
            aNb[p] = pack2(bN[g0], bN[g1]);
        }

        // ---- hh-GEMV inner loop: 6 LDS.128 reused across both sequences ----
        const float* wb = whh + j;
        #pragma unroll
        for (int k = 0; k < HH; ++k) {
            unsigned long long ha2 = dup2(ha[k]);
            unsigned long long hb2 = dup2(hb[k]);
            const ulonglong2* pr = (const ulonglong2*)(wb + k * G3);
            const ulonglong2* pz = (const ulonglong2*)(wb + k * G3 + 64);
            const ulonglong2* pn = (const ulonglong2*)(wb + k * G3 + 128);
            ulonglong2 r0 = pr[0], r1 = pr[1];
            ulonglong2 z0 = pz[0], z1 = pz[1];
            ulonglong2 n0 = pn[0], n1 = pn[1];
            FMA2(aRa[0], ha2, r0.x); FMA2(aRa[1], ha2, r0.y);
            FMA2(aRa[2], ha2, r1.x); FMA2(aRa[3], ha2, r1.y);
            FMA2(aRb[0], hb2, r0.x); FMA2(aRb[1], hb2, r0.y);
            FMA2(aRb[2], hb2, r1.x); FMA2(aRb[3], hb2, r1.y);
            FMA2(aZa[0], ha2, z0.x); FMA2(aZa[1], ha2, z0.y);
            FMA2(aZa[2], ha2, z1.x); FMA2(aZa[3], ha2, z1.y);
            FMA2(aZb[0], hb2, z0.x); FMA2(aZb[1], hb2, z0.y);
            FMA2(aZb[2], hb2, z1.x); FMA2(aZb[3], hb2, z1.y);
            FMA2(aNa[0], ha2, n0.x); FMA2(aNa[1], ha2, n0.y);
            FMA2(aNa[2], ha2, n1.x); FMA2(aNa[3], ha2, n1.y);
            FMA2(aNb[0], hb2, n0.x); FMA2(aNb[1], hb2, n0.y);
            FMA2(aNb[2], hb2, n1.x); FMA2(aNb[3], hb2, n1.y);
        }

        // ---- epilogue: activations + h update (new h -> hs) ----
        const float* wAn  = sm + OFF_WA + 128;
        const float* wBn  = sm + OFF_WB + 128;
        const float* bihn = sm + OFF_BIH + 128;
        #pragma unroll
        for (int p = 0; p < 4; ++p) {
            float2 rva = unpack2(aRa[p]), zva = unpack2(aZa[p]), nva = unpack2(aNa[p]);
            float2 rvb = unpack2(aRb[p]), zvb = unpack2(aZb[p]), nvb = unpack2(aNb[p]);
            #pragma unroll
            for (int u = 0; u < 2; ++u) {
                int g = j + 2 * p + u;
                float gra = u ? rva.y : rva.x, gza = u ? zva.y : zva.x, gna = u ? nva.y : nva.x;
                float grb = u ? rvb.y : rvb.x, gzb = u ? zvb.y : zvb.x, gnb = u ? nvb.y : nvb.x;
                float wan = wAn[g], bn = bihn[g];
                float gxa = fmaf(wan, xa0, bn);
                float gxb = fmaf(wan, xb0, bn);
                if (HASX1) {
                    float wbn = wBn[g];
                    gxa = fmaf(wbn, xa1, gxa);
                    gxb = fmaf(wbn, xb1, gxb);
                }
                float rsa = sigmoidf_(gra), zsa = sigmoidf_(gza);
                float rsb = sigmoidf_(grb), zsb = sigmoidf_(gzb);
                float na = tanhf_(fmaf(rsa, gna, gxa));
                float nb = tanhf_(fmaf(rsb, gnb, gxb));
                float2 hold = hs[g * NT + tid];
                float hna = na + zsa * (hold.x - na);
                float hnb = nb + zsb * (hold.y - nb);
                hs[g * NT + tid] = make_float2(hna, hnb);
            }
        }
    }

    // reload new h into registers
    #pragma unroll
    for (int k = 0; k < HH; ++k) {
        float2 v = hs[k * NT + tid];
        ha[k] = v.x; hb[k] = v.y;
    }
}

__device__ __forceinline__ void stage_weights(
    float* sm, int tid, const float* __restrict__ whh,
    const float* __restrict__ wih, int stride,
    const float* __restrict__ bih, const float* __restrict__ bhh)
{
    for (int idx = tid; idx < G3 * HH; idx += NT) {
        int g = idx >> 6, k = idx & 63;          // global whh is [g][k]
        sm[OFF_W + k * G3 + g] = whh[idx];
    }
    if (tid < G3) {
        sm[OFF_WA + tid]  = wih[tid * stride];
        sm[OFF_WB + tid]  = (stride == 2) ? wih[tid * 2 + 1] : 0.0f;
        sm[OFF_BIH + tid] = bih[tid];
        sm[OFF_BHH + tid] = bhh[tid];
    }
}

__global__ void __launch_bounds__(NT, 1) krnn_main(
    const float* __restrict__ X,
    const float* __restrict__ enc_w_ih, const float* __restrict__ enc_w_hh,
    const float* __restrict__ enc_b_ih, const float* __restrict__ enc_b_hh,
    const float* __restrict__ dec_w_ih, const float* __restrict__ dec_w_hh,
    const float* __restrict__ dec_b_ih, const float* __restrict__ dec_b_hh,
    const float* __restrict__ lin1_w,   const float* __restrict__ lin1_b)
{
    extern __shared__ float sm[];
    const int c   = blockIdx.y;
    const int tid = threadIdx.x;

    // stage ENCODER weights
    stage_weights(sm, tid, enc_w_hh + c * (G3 * HH), enc_w_ih + c * (G3 * 2), 2,
                  enc_b_ih + c * G3, enc_b_hh + c * G3);
    __syncthreads();

    const int seqa = (blockIdx.x * NT + tid) * 2;   // this thread: seqs (seqa, seqa+1)
    float2* hs = (float2*)(sm + OFF_HS);

    float ha[HH], hb[HH];
    #pragma unroll
    for (int k = 0; k < HH; ++k) {
        ha[k] = 0.0f; hb[k] = 0.0f;
        hs[k * NT + tid] = make_float2(0.0f, 0.0f);   // own slots only, no sync needed
    }

    // ---- encoder ----
    const int s = c + 3;
    const float2* hvp = (const float2*)g_hv;
    for (int st = 0; st < s; ++st) {
        float4 xv = *(const float4*)(hvp + (size_t)(c * TOUT + st) * BN + seqa);
        gru_step2<true>(ha, hb, sm, tid, xv.x, xv.y, xv.z, xv.w);
    }

    // restage DECODER weights over the same buffer
    __syncthreads();
    stage_weights(sm, tid, dec_w_hh + c * (G3 * HH), dec_w_ih + c * G3, 1,
                  dec_b_ih + c * G3, dec_b_hh + c * G3);
    if (tid < HH)  sm[OFF_L1W + tid] = lin1_w[c * HH + tid];
    if (tid == HH) sm[OFF_L1B] = lin1_b[c];
    __syncthreads();

    // ---- decoder ----
    float lva = X[(size_t)seqa * (TT * 2) + 22];          // X[seq, t=11, f=0]
    float lvb = X[(size_t)(seqa + 1) * (TT * 2) + 22];
    const float l1b = sm[OFF_L1B];
    for (int st = 0; st < TOUT; ++st) {
        gru_step2<false>(ha, hb, sm, tid, lva, 0.0f, lvb, 0.0f);
        float va = l1b, vb = l1b;
        #pragma unroll
        for (int k = 0; k < HH; ++k) {
            float w = sm[OFF_L1W + k];
            va = fmaf(ha[k], w, va);
            vb = fmaf(hb[k], w, vb);
        }
        *(float2*)&g_vals[(size_t)(c * TOUT + st) * BN + seqa] = make_float2(va, vb);
        lva = va; lvb = vb;
    }
}

// precompute encoder inputs hv[c][st][seq] = (x0,x1)
__global__ void __launch_bounds__(256) krnn_hv(
    const float* __restrict__ X,
    const float* __restrict__ lin2_w, const float* __restrict__ lin2_b)
{
    const int seq = blockIdx.x * 256 + threadIdx.x;
    float Xl[24];
    {
        const float4* xp = (const float4*)(X + (size_t)seq * (TT * 2));
        #pragma unroll
        for (int q = 0; q < 6; ++q) {
            float4 v = xp[q];
            Xl[4*q+0] = v.x; Xl[4*q+1] = v.y; Xl[4*q+2] = v.z; Xl[4*q+3] = v.w;
        }
    }
    float2* hvp = (float2*)g_hv;
    for (int c = 0; c < CC; ++c) {
        const int s = c + 3;
        for (int st = 0; st < s; ++st) {
            float b = lin2_b[c * 12 + st];
            float x0 = b, x1 = b;
            #pragma unroll
            for (int t = 0; t < TT; ++t) {
                float w = lin2_w[c * 144 + st * 12 + t];
                x0 = fmaf(Xl[2 * t],     w, x0);
                x1 = fmaf(Xl[2 * t + 1], w, x1);
            }
            hvp[(size_t)(c * TOUT + st) * BN + seq] = make_float2(x0, x1);
        }
    }
}

__global__ void __launch_bounds__(256) krnn_combine(
    const float* __restrict__ X,
    const float* __restrict__ embed1,
    float* __restrict__ out)
{
    const int seq = blockIdx.x * 256 + threadIdx.x;

    float q[TT];
    #pragma unroll
    for (int t = 0; t < TT; ++t) q[t] = X[(size_t)seq * (TT * 2) + t * 2];

    float wq[TOUT];
    #pragma unroll
    for (int o = 0; o < TOUT; ++o) {
        float a = 0.0f;
        #pragma unroll
        for (int t = 0; t < TT; ++t) a = fmaf(q[t], embed1[t * TOUT + o], a);
        wq[o] = a;
    }

    float ov[TOUT * CC];
    #pragma unroll
    for (int cc = 0; cc < CC; ++cc)
        #pragma unroll
        for (int o = 0; o < TOUT; ++o)
            ov[o * CC + cc] = g_vals[((size_t)cc * TOUT + o) * BN + seq];

    float wc[CC];
    #pragma unroll
    for (int cc = 0; cc < CC; ++cc) {
        float a = 0.0f;
        #pragma unroll
        for (int o = 0; o < TOUT; ++o) a = fmaf(wq[o], ov[o * CC + cc], a);
        wc[cc] = a;
    }

    float m = wc[0];
    #pragma unroll
    for (int cc = 1; cc < CC; ++cc) m = fmaxf(m, wc[cc]);
    float e[CC]; float ssum = 0.0f;
    #pragma unroll
    for (int cc = 0; cc < CC; ++cc) { e[cc] = expf(wc[cc] - m); ssum += e[cc]; }
    float inv = 1.0f / ssum;

    #pragma unroll
    for (int o = 0; o < TOUT; ++o) {
        float a = 0.0f;
        #pragma unroll
        for (int cc = 0; cc < CC; ++cc) a = fmaf(ov[o * CC + cc], e[cc], a);
        out[(size_t)seq * TOUT + o] = a * inv;
    }
}

extern "C" void kernel_launch(void* const* d_in, const int* in_sizes, int n_in,
                              void* d_out, int out_size)
{
    // input order: A, X, enc_w_ih, enc_w_hh, enc_b_ih, enc_b_hh,
    //              dec_w_ih, dec_w_hh, dec_b_ih, dec_b_hh,
    //              lin1_w, lin1_b, lin2_w, lin2_b, embed1
    const float* X        = (const float*)d_in[1];
    const float* enc_w_ih = (const float*)d_in[2];
    const float* enc_w_hh = (const float*)d_in[3];
    const float* enc_b_ih = (const float*)d_in[4];
    const float* enc_b_hh = (const float*)d_in[5];
    const float* dec_w_ih = (const float*)d_in[6];
    const float* dec_w_hh = (const float*)d_in[7];
    const float* dec_b_ih = (const float*)d_in[8];
    const float* dec_b_hh = (const float*)d_in[9];
    const float* lin1_w   = (const float*)d_in[10];
    const float* lin1_b   = (const float*)d_in[11];
    const float* lin2_w   = (const float*)d_in[12];
    const float* lin2_b   = (const float*)d_in[13];
    const float* embed1   = (const float*)d_in[14];

    cudaFuncSetAttribute(krnn_main, cudaFuncAttributeMaxDynamicSharedMemorySize, SMEM_BYTES);

    krnn_hv<<<BN / 256, 256>>>(X, lin2_w, lin2_b);

    dim3 grid(BN / (NT * 2), CC);
    krnn_main<<<grid, NT, SMEM_BYTES>>>(
        X, enc_w_ih, enc_w_hh, enc_b_ih, enc_b_hh,
        dec_w_ih, dec_w_hh, dec_b_ih, dec_b_hh,
        lin1_w, lin1_b);

    krnn_combine<<<BN / 256, 256>>>(X, embed1, (float*)d_out);
}

// round 3
// speedup vs baseline: 1.5211x; 1.0649x over previous
#include <cuda_runtime.h>

// Problem constants (fixed by the dataset)
#define BN    131072            // B*N
#define TT    12
#define HH    64
#define G3    192               // 3*H
#define CC    10
#define TOUT  12
#define NT    256               // threads per block (main kernel)

// ---- shared layout (floats) ----
#define OFF_W    0              // whh^T staged k-major [k*192 + g], 12288 floats
#define OFF_WA   12288          // w_ih feature0 [192]
#define OFF_WB   12480          // w_ih feature1 [192]
#define OFF_BIH  12672          // [192]
#define OFF_BHH  12864          // [192]
#define OFF_L1W  13056          // [64]
#define OFF_L1B  13120          // [1]
#define OFF_HS   13124          // h mirror: float2[64][NT]
#define SMEM_FLOATS (OFF_HS + HH*NT*2)
#define SMEM_BYTES  (SMEM_FLOATS*4)

// device-global scratch
__device__ float g_hv[(size_t)CC * TOUT * BN * 2];   // encoder inputs (x0,x1) pairs
__device__ float g_vals[(size_t)CC * TOUT * BN];     // decoder outputs

// packed f32x2 FMA (sm_103a FFMA2)
#define FMA2(acc, a, b) asm("fma.rn.f32x2 %0, %1, %2, %0;" : "+l"(acc) : "l"(a), "l"(b))

__device__ __forceinline__ unsigned long long pack2(float lo, float hi) {
    unsigned long long v;
    asm("mov.b64 %0, {%1, %2};" : "=l"(v) : "f"(lo), "f"(hi));
    return v;
}
__device__ __forceinline__ unsigned long long dup2(float x) {
    unsigned long long v;
    asm("mov.b64 %0, {%1, %1};" : "=l"(v) : "f"(x));
    return v;
}
__device__ __forceinline__ float2 unpack2(unsigned long long v) {
    float2 r;
    asm("mov.b64 {%0, %1}, %2;" : "=f"(r.x), "=f"(r.y) : "l"(v));
    return r;
}

// sigmoid via single-MUFU tanh.approx: sigma(x) = 0.5 + 0.5*tanh(x/2)
__device__ __forceinline__ float sigmoid_fast(float x) {
    float t;
    float y = 0.5f * x;
    asm("tanh.approx.f32 %0, %1;" : "=f"(t) : "f"(y));
    return fmaf(0.5f, t, 0.5f);
}
// precise-ish tanh for the n gate (feeds the recurrence)
__device__ __forceinline__ float tanhf_(float x) {
    return __fdividef(2.0f, 1.0f + __expf(-2.0f * x)) - 1.0f;
}

// One GRU step for TWO sequences (a,b) per thread.
// ha/hb: register-resident old h. hs (in smem): pairs {a,b} at [k*NT + tid];
// holds old h at entry (== registers), epilogue writes new h, reload at end.
template<bool HASX1>
__device__ __forceinline__ void gru_step2(
    float (&ha)[HH], float (&hb)[HH], float* sm, int tid,
    float xa0, float xa1, float xb0, float xb1)
{
    const float* whh = sm + OFF_W;
    float2* hs = (float2*)(sm + OFF_HS);

    #pragma unroll 1
    for (int j = 0; j < HH; j += 8) {
        // ---- stage per-block init coefficients (vectorized shared loads) ----
        float wAr[8], wAz[8], wBr[8], wBz[8], bR[8], bZ[8], bN[8];
        *(float4*)(wAr)     = *(const float4*)(sm + OFF_WA + j);
        *(float4*)(wAr + 4) = *(const float4*)(sm + OFF_WA + j + 4);
        *(float4*)(wAz)     = *(const float4*)(sm + OFF_WA + 64 + j);
        *(float4*)(wAz + 4) = *(const float4*)(sm + OFF_WA + 64 + j + 4);
        if (HASX1) {
            *(float4*)(wBr)     = *(const float4*)(sm + OFF_WB + j);
            *(float4*)(wBr + 4) = *(const float4*)(sm + OFF_WB + j + 4);
            *(float4*)(wBz)     = *(const float4*)(sm + OFF_WB + 64 + j);
            *(float4*)(wBz + 4) = *(const float4*)(sm + OFF_WB + 64 + j + 4);
        }
        {
            float4 i0 = *(const float4*)(sm + OFF_BIH + j);
            float4 i1 = *(const float4*)(sm + OFF_BIH + j + 4);
            float4 h0 = *(const float4*)(sm + OFF_BHH + j);
            float4 h1 = *(const float4*)(sm + OFF_BHH + j + 4);
            bR[0]=i0.x+h0.x; bR[1]=i0.y+h0.y; bR[2]=i0.z+h0.z; bR[3]=i0.w+h0.w;
            bR[4]=i1.x+h1.x; bR[5]=i1.y+h1.y; bR[6]=i1.z+h1.z; bR[7]=i1.w+h1.w;
            i0 = *(const float4*)(sm + OFF_BIH + 64 + j);
            i1 = *(const float4*)(sm + OFF_BIH + 64 + j + 4);
            h0 = *(const float4*)(sm + OFF_BHH + 64 + j);
            h1 = *(const float4*)(sm + OFF_BHH + 64 + j + 4);
            bZ[0]=i0.x+h0.x; bZ[1]=i0.y+h0.y; bZ[2]=i0.z+h0.z; bZ[3]=i0.w+h0.w;
            bZ[4]=i1.x+h1.x; bZ[5]=i1.y+h1.y; bZ[6]=i1.z+h1.z; bZ[7]=i1.w+h1.w;
            h0 = *(const float4*)(sm + OFF_BHH + 128 + j);
            h1 = *(const float4*)(sm + OFF_BHH + 128 + j + 4);
            bN[0]=h0.x; bN[1]=h0.y; bN[2]=h0.z; bN[3]=h0.w;
            bN[4]=h1.x; bN[5]=h1.y; bN[6]=h1.z; bN[7]=h1.w;
        }

        // ---- accumulator init: gx(r,z)+b_hh ; b_hh only for n ----
        unsigned long long aRa[4], aZa[4], aNa[4], aRb[4], aZb[4], aNb[4];
        #pragma unroll
        for (int p = 0; p < 4; ++p) {
            int g0 = 2 * p, g1 = g0 + 1;
            float ra0 = fmaf(wAr[g0], xa0, bR[g0]);
            float ra1 = fmaf(wAr[g1], xa0, bR[g1]);
            float za0 = fmaf(wAz[g0], xa0, bZ[g0]);
            float za1 = fmaf(wAz[g1], xa0, bZ[g1]);
            float rb0 = fmaf(wAr[g0], xb0, bR[g0]);
            float rb1 = fmaf(wAr[g1], xb0, bR[g1]);
            float zb0 = fmaf(wAz[g0], xb0, bZ[g0]);
            float zb1 = fmaf(wAz[g1], xb0, bZ[g1]);
            if (HASX1) {
                ra0 = fmaf(wBr[g0], xa1, ra0); ra1 = fmaf(wBr[g1], xa1, ra1);
                za0 = fmaf(wBz[g0], xa1, za0); za1 = fmaf(wBz[g1], xa1, za1);
                rb0 = fmaf(wBr[g0], xb1, rb0); rb1 = fmaf(wBr[g1], xb1, rb1);
                zb0 = fmaf(wBz[g0], xb1, zb0); zb1 = fmaf(wBz[g1], xb1, zb1);
            }
            aRa[p] = pack2(ra0, ra1); aZa[p] = pack2(za0, za1);
            aRb[p] = pack2(rb0, rb1); aZb[p] = pack2(zb0, zb1);
            aNa[p] = pack2(bN[g0], bN[g1]);
            aNb[p] = pack2(bN[g0], bN[g1]);
        }

        // ---- hh-GEMV inner loop: 6 LDS.128 reused across both sequences ----
        const float* wb = whh + j;
        #pragma unroll
        for (int k = 0; k < HH; ++k) {
            unsigned long long ha2 = dup2(ha[k]);
            unsigned long long hb2 = dup2(hb[k]);
            const ulonglong2* pr = (const ulonglong2*)(wb + k * G3);
            const ulonglong2* pz = (const ulonglong2*)(wb + k * G3 + 64);
            const ulonglong2* pn = (const ulonglong2*)(wb + k * G3 + 128);
            ulonglong2 r0 = pr[0], r1 = pr[1];
            ulonglong2 z0 = pz[0], z1 = pz[1];
            ulonglong2 n0 = pn[0], n1 = pn[1];
            FMA2(aRa[0], ha2, r0.x); FMA2(aRa[1], ha2, r0.y);
            FMA2(aRa[2], ha2, r1.x); FMA2(aRa[3], ha2, r1.y);
            FMA2(aRb[0], hb2, r0.x); FMA2(aRb[1], hb2, r0.y);
            FMA2(aRb[2], hb2, r1.x); FMA2(aRb[3], hb2, r1.y);
            FMA2(aZa[0], ha2, z0.x); FMA2(aZa[1], ha2, z0.y);
            FMA2(aZa[2], ha2, z1.x); FMA2(aZa[3], ha2, z1.y);
            FMA2(aZb[0], hb2, z0.x); FMA2(aZb[1], hb2, z0.y);
            FMA2(aZb[2], hb2, z1.x); FMA2(aZb[3], hb2, z1.y);
            FMA2(aNa[0], ha2, n0.x); FMA2(aNa[1], ha2, n0.y);
            FMA2(aNa[2], ha2, n1.x); FMA2(aNa[3], ha2, n1.y);
            FMA2(aNb[0], hb2, n0.x); FMA2(aNb[1], hb2, n0.y);
            FMA2(aNb[2], hb2, n1.x); FMA2(aNb[3], hb2, n1.y);
        }

        // ---- epilogue: activations + h update (new h -> hs) ----
        const float* wAn  = sm + OFF_WA + 128;
        const float* wBn  = sm + OFF_WB + 128;
        const float* bihn = sm + OFF_BIH + 128;
        #pragma unroll
        for (int p = 0; p < 4; ++p) {
            float2 rva = unpack2(aRa[p]), zva = unpack2(aZa[p]), nva = unpack2(aNa[p]);
            float2 rvb = unpack2(aRb[p]), zvb = unpack2(aZb[p]), nvb = unpack2(aNb[p]);
            #pragma unroll
            for (int u = 0; u < 2; ++u) {
                int g = j + 2 * p + u;
                float gra = u ? rva.y : rva.x, gza = u ? zva.y : zva.x, gna = u ? nva.y : nva.x;
                float grb = u ? rvb.y : rvb.x, gzb = u ? zvb.y : zvb.x, gnb = u ? nvb.y : nvb.x;
                float wan = wAn[g], bn = bihn[g];
                float gxa = fmaf(wan, xa0, bn);
                float gxb = fmaf(wan, xb0, bn);
                if (HASX1) {
                    float wbn = wBn[g];
                    gxa = fmaf(wbn, xa1, gxa);
                    gxb = fmaf(wbn, xb1, gxb);
                }
                float rsa = sigmoid_fast(gra), zsa = sigmoid_fast(gza);
                float rsb = sigmoid_fast(grb), zsb = sigmoid_fast(gzb);
                float na = tanhf_(fmaf(rsa, gna, gxa));
                float nb = tanhf_(fmaf(rsb, gnb, gxb));
                float2 hold = hs[g * NT + tid];
                float hna = na + zsa * (hold.x - na);
                float hnb = nb + zsb * (hold.y - nb);
                hs[g * NT + tid] = make_float2(hna, hnb);
            }
        }
    }

    // reload new h into registers
    #pragma unroll
    for (int k = 0; k < HH; ++k) {
        float2 v = hs[k * NT + tid];
        ha[k] = v.x; hb[k] = v.y;
    }
}

__device__ __forceinline__ void stage_weights(
    float* sm, int tid, const float* __restrict__ whh,
    const float* __restrict__ wih, int stride,
    const float* __restrict__ bih, const float* __restrict__ bhh)
{
    for (int idx = tid; idx < G3 * HH; idx += NT) {
        int g = idx >> 6, k = idx & 63;          // global whh is [g][k]
        sm[OFF_W + k * G3 + g] = whh[idx];
    }
    if (tid < G3) {
        sm[OFF_WA + tid]  = wih[tid * stride];
        sm[OFF_WB + tid]  = (stride == 2) ? wih[tid * 2 + 1] : 0.0f;
        sm[OFF_BIH + tid] = bih[tid];
        sm[OFF_BHH + tid] = bhh[tid];
    }
}

__global__ void __launch_bounds__(NT, 1) krnn_main(
    const float* __restrict__ X,
    const float* __restrict__ enc_w_ih, const float* __restrict__ enc_w_hh,
    const float* __restrict__ enc_b_ih, const float* __restrict__ enc_b_hh,
    const float* __restrict__ dec_w_ih, const float* __restrict__ dec_w_hh,
    const float* __restrict__ dec_b_ih, const float* __restrict__ dec_b_hh,
    const float* __restrict__ lin1_w,   const float* __restrict__ lin1_b)
{
    extern __shared__ float sm[];
    // longest-first channel order: c=9 (24 steps) dispatched first,
    // so the tail wave runs the shortest blocks.
    const int c   = (CC - 1) - blockIdx.y;
    const int tid = threadIdx.x;

    // stage ENCODER weights
    stage_weights(sm, tid, enc_w_hh + c * (G3 * HH), enc_w_ih + c * (G3 * 2), 2,
                  enc_b_ih + c * G3, enc_b_hh + c * G3);
    __syncthreads();

    const int seqa = (blockIdx.x * NT + tid) * 2;   // this thread: seqs (seqa, seqa+1)
    float2* hs = (float2*)(sm + OFF_HS);

    // prefetch decoder seed values early (hide DRAM latency under encoder)
    float lva = X[(size_t)seqa * (TT * 2) + 22];          // X[seq, t=11, f=0]
    float lvb = X[(size_t)(seqa + 1) * (TT * 2) + 22];

    float ha[HH], hb[HH];
    #pragma unroll
    for (int k = 0; k < HH; ++k) {
        ha[k] = 0.0f; hb[k] = 0.0f;
        hs[k * NT + tid] = make_float2(0.0f, 0.0f);   // own slots only, no sync needed
    }

    // ---- encoder ----
    const int s = c + 3;
    const float2* hvp = (const float2*)g_hv;
    for (int st = 0; st < s; ++st) {
        float4 xv = *(const float4*)(hvp + (size_t)(c * TOUT + st) * BN + seqa);
        gru_step2<true>(ha, hb, sm, tid, xv.x, xv.y, xv.z, xv.w);
    }

    // restage DECODER weights over the same buffer
    __syncthreads();
    stage_weights(sm, tid, dec_w_hh + c * (G3 * HH), dec_w_ih + c * G3, 1,
                  dec_b_ih + c * G3, dec_b_hh + c * G3);
    if (tid < HH)  sm[OFF_L1W + tid] = lin1_w[c * HH + tid];
    if (tid == HH) sm[OFF_L1B] = lin1_b[c];
    __syncthreads();

    // ---- decoder ----
    const float l1b = sm[OFF_L1B];
    for (int st = 0; st < TOUT; ++st) {
        gru_step2<false>(ha, hb, sm, tid, lva, 0.0f, lvb, 0.0f);
        float va = l1b, vb = l1b;
        #pragma unroll
        for (int k = 0; k < HH; ++k) {
            float w = sm[OFF_L1W + k];
            va = fmaf(ha[k], w, va);
            vb = fmaf(hb[k], w, vb);
        }
        *(float2*)&g_vals[(size_t)(c * TOUT + st) * BN + seqa] = make_float2(va, vb);
        lva = va; lvb = vb;
    }
}

// precompute encoder inputs hv[c][st][seq] = (x0,x1)
__global__ void __launch_bounds__(256) krnn_hv(
    const float* __restrict__ X,
    const float* __restrict__ lin2_w, const float* __restrict__ lin2_b)
{
    const int seq = blockIdx.x * 256 + threadIdx.x;
    float Xl[24];
    {
        const float4* xp = (const float4*)(X + (size_t)seq * (TT * 2));
        #pragma unroll
        for (int q = 0; q < 6; ++q) {
            float4 v = xp[q];
            Xl[4*q+0] = v.x; Xl[4*q+1] = v.y; Xl[4*q+2] = v.z; Xl[4*q+3] = v.w;
        }
    }
    float2* hvp = (float2*)g_hv;
    for (int c = 0; c < CC; ++c) {
        const int s = c + 3;
        for (int st = 0; st < s; ++st) {
            float b = lin2_b[c * 12 + st];
            float x0 = b, x1 = b;
            #pragma unroll
            for (int t = 0; t < TT; ++t) {
                float w = lin2_w[c * 144 + st * 12 + t];
                x0 = fmaf(Xl[2 * t],     w, x0);
                x1 = fmaf(Xl[2 * t + 1], w, x1);
            }
            hvp[(size_t)(c * TOUT + st) * BN + seq] = make_float2(x0, x1);
        }
    }
}

__global__ void __launch_bounds__(256) krnn_combine(
    const float* __restrict__ X,
    const float* __restrict__ embed1,
    float* __restrict__ out)
{
    const int seq = blockIdx.x * 256 + threadIdx.x;

    float q[TT];
    #pragma unroll
    for (int t = 0; t < TT; ++t) q[t] = X[(size_t)seq * (TT * 2) + t * 2];

    float wq[TOUT];
    #pragma unroll
    for (int o = 0; o < TOUT; ++o) {
        float a = 0.0f;
        #pragma unroll
        for (int t = 0; t < TT; ++t) a = fmaf(q[t], embed1[t * TOUT + o], a);
        wq[o] = a;
    }

    float ov[TOUT * CC];
    #pragma unroll
    for (int cc = 0; cc < CC; ++cc)
        #pragma unroll
        for (int o = 0; o < TOUT; ++o)
            ov[o * CC + cc] = g_vals[((size_t)cc * TOUT + o) * BN + seq];

    float wc[CC];
    #pragma unroll
    for (int cc = 0; cc < CC; ++cc) {
        float a = 0.0f;
        #pragma unroll
        for (int o = 0; o < TOUT; ++o) a = fmaf(wq[o], ov[o * CC + cc], a);
        wc[cc] = a;
    }

    float m = wc[0];
    #pragma unroll
    for (int cc = 1; cc < CC; ++cc) m = fmaxf(m, wc[cc]);
    float e[CC]; float ssum = 0.0f;
    #pragma unroll
    for (int cc = 0; cc < CC; ++cc) { e[cc] = expf(wc[cc] - m); ssum += e[cc]; }
    float inv = 1.0f / ssum;

    #pragma unroll
    for (int o = 0; o < TOUT; ++o) {
        float a = 0.0f;
        #pragma unroll
        for (int cc = 0; cc < CC; ++cc) a = fmaf(ov[o * CC + cc], e[cc], a);
        out[(size_t)seq * TOUT + o] = a * inv;
    }
}

extern "C" void kernel_launch(void* const* d_in, const int* in_sizes, int n_in,
                              void* d_out, int out_size)
{
    // input order: A, X, enc_w_ih, enc_w_hh, enc_b_ih, enc_b_hh,
    //              dec_w_ih, dec_w_hh, dec_b_ih, dec_b_hh,
    //              lin1_w, lin1_b, lin2_w, lin2_b, embed1
    const float* X        = (const float*)d_in[1];
    const float* enc_w_ih = (const float*)d_in[2];
    const float* enc_w_hh = (const float*)d_in[3];
    const float* enc_b_ih = (const float*)d_in[4];
    const float* enc_b_hh = (const float*)d_in[5];
    const float* dec_w_ih = (const float*)d_in[6];
    const float* dec_w_hh = (const float*)d_in[7];
    const float* dec_b_ih = (const float*)d_in[8];
    const float* dec_b_hh = (const float*)d_in[9];
    const float* lin1_w   = (const float*)d_in[10];
    const float* lin1_b   = (const float*)d_in[11];
    const float* lin2_w   = (const float*)d_in[12];
    const float* lin2_b   = (const float*)d_in[13];
    const float* embed1   = (const float*)d_in[14];

    cudaFuncSetAttribute(krnn_main, cudaFuncAttributeMaxDynamicSharedMemorySize, SMEM_BYTES);

    krnn_hv<<<BN / 256, 256>>>(X, lin2_w, lin2_b);

    dim3 grid(BN / (NT * 2), CC);
    krnn_main<<<grid, NT, SMEM_BYTES>>>(
        X, enc_w_ih, enc_w_hh, enc_b_ih, enc_b_hh,
        dec_w_ih, dec_w_hh, dec_b_ih, dec_b_hh,
        lin1_w, lin1_b);

    krnn_combine<<<BN / 256, 256>>>(X, embed1, (float*)d_out);
}

// round 4
// speedup vs baseline: 1.6413x; 1.0790x over previous
#include <cuda_runtime.h>

// Problem constants (fixed by the dataset)
#define BN    131072            // B*N
#define TT    12
#define HH    64
#define G3    192               // 3*H
#define CC    10
#define TOUT  12
#define NT    256               // threads per block (main kernel)

// ---- shared layout (floats) ----
#define OFF_W     0             // whh^T staged k-major [k*192 + g], 12288 floats
#define OFF_WA    12288         // w_ih feature0 [192]
#define OFF_WB    12480         // w_ih feature1 [192]
#define OFF_BRZ   12672         // b_ih+b_hh for r,z gates [128]
#define OFF_BIHN  12800         // b_ih for n gates [64]
#define OFF_BHHN  12864         // b_hh for n gates [64]
#define OFF_L1W   12928         // [64]
#define OFF_L1B   12992         // [1]
#define OFF_HS    12996         // h state: float2[64][NT]  (even index -> 8B aligned)
#define SMEM_FLOATS (OFF_HS + HH*NT*2)
#define SMEM_BYTES  (SMEM_FLOATS*4)

// device-global scratch
__device__ float g_hv[(size_t)CC * TOUT * BN * 2];   // encoder inputs (x0,x1) pairs
__device__ float g_vals[(size_t)CC * TOUT * BN];     // decoder outputs

// packed f32x2 FMA (sm_103a FFMA2)
#define FMA2(acc, a, b) asm("fma.rn.f32x2 %0, %1, %2, %0;" : "+l"(acc) : "l"(a), "l"(b))

__device__ __forceinline__ unsigned long long pack2(float lo, float hi) {
    unsigned long long v;
    asm("mov.b64 %0, {%1, %2};" : "=l"(v) : "f"(lo), "f"(hi));
    return v;
}
__device__ __forceinline__ unsigned long long dup2(float x) {
    unsigned long long v;
    asm("mov.b64 %0, {%1, %1};" : "=l"(v) : "f"(x));
    return v;
}
__device__ __forceinline__ float2 unpack2(unsigned long long v) {
    float2 r;
    asm("mov.b64 {%0, %1}, %2;" : "=f"(r.x), "=f"(r.y) : "l"(v));
    return r;
}

// sigmoid via single-MUFU tanh.approx: sigma(x) = 0.5 + 0.5*tanh(x/2)
__device__ __forceinline__ float sigmoid_fast(float x) {
    float t;
    float y = 0.5f * x;
    asm("tanh.approx.f32 %0, %1;" : "=f"(t) : "f"(y));
    return fmaf(0.5f, t, 0.5f);
}
// n gate: direct single-MUFU tanh
__device__ __forceinline__ float tanh_fast(float x) {
    float t;
    asm("tanh.approx.f32 %0, %1;" : "=f"(t) : "f"(x));
    return t;
}

// One GRU step for TWO sequences (a,b) per thread.
// ha/hb: register-resident old h. hs (smem float2[64][NT]): holds old h at entry
// (invariant maintained by previous step's epilogue), epilogue writes new h,
// reload at end. wrot: per-warp j-block rotation to desynchronize epilogues.
template<bool HASX1>
__device__ __forceinline__ void gru_step2(
    float (&ha)[HH], float (&hb)[HH], float* sm, int tid, int wrot,
    float xa0, float xa1, float xb0, float xb1)
{
    const float* whh = sm + OFF_W;
    float2* hs = (float2*)(sm + OFF_HS);

    #pragma unroll 1
    for (int jb = 0; jb < 8; ++jb) {
        const int j = ((jb + wrot) & 7) << 3;

        // ---- stage per-block coefficients (vectorized shared loads) ----
        float wAr[8], wAz[8], wBr[8], wBz[8], bR[8], bZ[8], bN[8];
        *(float4*)(wAr)     = *(const float4*)(sm + OFF_WA + j);
        *(float4*)(wAr + 4) = *(const float4*)(sm + OFF_WA + j + 4);
        *(float4*)(wAz)     = *(const float4*)(sm + OFF_WA + 64 + j);
        *(float4*)(wAz + 4) = *(const float4*)(sm + OFF_WA + 64 + j + 4);
        if (HASX1) {
            *(float4*)(wBr)     = *(const float4*)(sm + OFF_WB + j);
            *(float4*)(wBr + 4) = *(const float4*)(sm + OFF_WB + j + 4);
            *(float4*)(wBz)     = *(const float4*)(sm + OFF_WB + 64 + j);
            *(float4*)(wBz + 4) = *(const float4*)(sm + OFF_WB + 64 + j + 4);
        }
        *(float4*)(bR)     = *(const float4*)(sm + OFF_BRZ + j);
        *(float4*)(bR + 4) = *(const float4*)(sm + OFF_BRZ + j + 4);
        *(float4*)(bZ)     = *(const float4*)(sm + OFF_BRZ + 64 + j);
        *(float4*)(bZ + 4) = *(const float4*)(sm + OFF_BRZ + 64 + j + 4);
        *(float4*)(bN)     = *(const float4*)(sm + OFF_BHHN + j);
        *(float4*)(bN + 4) = *(const float4*)(sm + OFF_BHHN + j + 4);

        // ---- accumulator init: gx(r,z)+biases ; b_hh only for n ----
        unsigned long long aRa[4], aZa[4], aNa[4], aRb[4], aZb[4], aNb[4];
        #pragma unroll
        for (int p = 0; p < 4; ++p) {
            int g0 = 2 * p, g1 = g0 + 1;
            float ra0 = fmaf(wAr[g0], xa0, bR[g0]);
            float ra1 = fmaf(wAr[g1], xa0, bR[g1]);
            float za0 = fmaf(wAz[g0], xa0, bZ[g0]);
            float za1 = fmaf(wAz[g1], xa0, bZ[g1]);
            float rb0 = fmaf(wAr[g0], xb0, bR[g0]);
            float rb1 = fmaf(wAr[g1], xb0, bR[g1]);
            float zb0 = fmaf(wAz[g0], xb0, bZ[g0]);
            float zb1 = fmaf(wAz[g1], xb0, bZ[g1]);
            if (HASX1) {
                ra0 = fmaf(wBr[g0], xa1, ra0); ra1 = fmaf(wBr[g1], xa1, ra1);
                za0 = fmaf(wBz[g0], xa1, za0); za1 = fmaf(wBz[g1], xa1, za1);
                rb0 = fmaf(wBr[g0], xb1, rb0); rb1 = fmaf(wBr[g1], xb1, rb1);
                zb0 = fmaf(wBz[g0], xb1, zb0); zb1 = fmaf(wBz[g1], xb1, zb1);
            }
            aRa[p] = pack2(ra0, ra1); aZa[p] = pack2(za0, za1);
            aRb[p] = pack2(rb0, rb1); aZb[p] = pack2(zb0, zb1);
            aNa[p] = pack2(bN[g0], bN[g1]);
            aNb[p] = pack2(bN[g0], bN[g1]);
        }

        // ---- hh-GEMV inner loop: 6 LDS.128 reused across both sequences ----
        const float* wb = whh + j;
        #pragma unroll
        for (int k = 0; k < HH; ++k) {
            unsigned long long ha2 = dup2(ha[k]);
            unsigned long long hb2 = dup2(hb[k]);
            const ulonglong2* pr = (const ulonglong2*)(wb + k * G3);
            const ulonglong2* pz = (const ulonglong2*)(wb + k * G3 + 64);
            const ulonglong2* pn = (const ulonglong2*)(wb + k * G3 + 128);
            ulonglong2 r0 = pr[0], r1 = pr[1];
            ulonglong2 z0 = pz[0], z1 = pz[1];
            ulonglong2 n0 = pn[0], n1 = pn[1];
            FMA2(aRa[0], ha2, r0.x); FMA2(aRa[1], ha2, r0.y);
            FMA2(aRa[2], ha2, r1.x); FMA2(aRa[3], ha2, r1.y);
            FMA2(aRb[0], hb2, r0.x); FMA2(aRb[1], hb2, r0.y);
            FMA2(aRb[2], hb2, r1.x); FMA2(aRb[3], hb2, r1.y);
            FMA2(aZa[0], ha2, z0.x); FMA2(aZa[1], ha2, z0.y);
            FMA2(aZa[2], ha2, z1.x); FMA2(aZa[3], ha2, z1.y);
            FMA2(aZb[0], hb2, z0.x); FMA2(aZb[1], hb2, z0.y);
            FMA2(aZb[2], hb2, z1.x); FMA2(aZb[3], hb2, z1.y);
            FMA2(aNa[0], ha2, n0.x); FMA2(aNa[1], ha2, n0.y);
            FMA2(aNa[2], ha2, n1.x); FMA2(aNa[3], ha2, n1.y);
            FMA2(aNb[0], hb2, n0.x); FMA2(aNb[1], hb2, n0.y);
            FMA2(aNb[2], hb2, n1.x); FMA2(aNb[3], hb2, n1.y);
        }

        // ---- epilogue: activations + h update (new h -> hs) ----
        const float* wAn  = sm + OFF_WA + 128;
        const float* wBn  = sm + OFF_WB + 128;
        const float* bihn = sm + OFF_BIHN;
        #pragma unroll
        for (int p = 0; p < 4; ++p) {
            float2 rva = unpack2(aRa[p]), zva = unpack2(aZa[p]), nva = unpack2(aNa[p]);
            float2 rvb = unpack2(aRb[p]), zvb = unpack2(aZb[p]), nvb = unpack2(aNb[p]);
            #pragma unroll
            for (int u = 0; u < 2; ++u) {
                int g = j + 2 * p + u;
                float gra = u ? rva.y : rva.x, gza = u ? zva.y : zva.x, gna = u ? nva.y : nva.x;
                float grb = u ? rvb.y : rvb.x, gzb = u ? zvb.y : zvb.x, gnb = u ? nvb.y : nvb.x;
                float wan = wAn[g], bn = bihn[g];
                float gxa = fmaf(wan, xa0, bn);
                float gxb = fmaf(wan, xb0, bn);
                if (HASX1) {
                    float wbn = wBn[g];
                    gxa = fmaf(wbn, xa1, gxa);
                    gxb = fmaf(wbn, xb1, gxb);
                }
                float rsa = sigmoid_fast(gra), zsa = sigmoid_fast(gza);
                float rsb = sigmoid_fast(grb), zsb = sigmoid_fast(gzb);
                float na = tanh_fast(fmaf(rsa, gna, gxa));
                float nb = tanh_fast(fmaf(rsb, gnb, gxb));
                float2 hold = hs[g * NT + tid];
                float hna = na + zsa * (hold.x - na);
                float hnb = nb + zsb * (hold.y - nb);
                hs[g * NT + tid] = make_float2(hna, hnb);
            }
        }
    }

    // reload new h into registers
    #pragma unroll
    for (int k = 0; k < HH; ++k) {
        float2 v = hs[k * NT + tid];
        ha[k] = v.x; hb[k] = v.y;
    }
}

__device__ __forceinline__ void stage_weights(
    float* sm, int tid, const float* __restrict__ whh,
    const float* __restrict__ wih, int stride,
    const float* __restrict__ bih, const float* __restrict__ bhh)
{
    for (int idx = tid; idx < G3 * HH; idx += NT) {
        int g = idx >> 6, k = idx & 63;          // global whh is [g][k]
        sm[OFF_W + k * G3 + g] = whh[idx];
    }
    if (tid < G3) {
        sm[OFF_WA + tid]  = wih[tid * stride];
        sm[OFF_WB + tid]  = (stride == 2) ? wih[tid * 2 + 1] : 0.0f;
        float bi = bih[tid], bh = bhh[tid];
        if (tid < 128) {
            sm[OFF_BRZ + tid] = bi + bh;
        } else {
            sm[OFF_BIHN + tid - 128] = bi;
            sm[OFF_BHHN + tid - 128] = bh;
        }
    }
}

__global__ void __launch_bounds__(NT, 1) krnn_main(
    const float* __restrict__ X,
    const float* __restrict__ enc_w_ih, const float* __restrict__ enc_w_hh,
    const float* __restrict__ enc_b_ih, const float* __restrict__ enc_b_hh,
    const float* __restrict__ dec_w_ih, const float* __restrict__ dec_w_hh,
    const float* __restrict__ dec_b_ih, const float* __restrict__ dec_b_hh,
    const float* __restrict__ lin1_w,   const float* __restrict__ lin1_b)
{
    extern __shared__ float sm[];
    // longest-first channel order: c=9 (24 steps) dispatched first,
    // so the tail wave runs the shortest blocks.
    const int c    = (CC - 1) - blockIdx.y;
    const int tid  = threadIdx.x;
    const int wrot = tid >> 5;     // per-warp j-block rotation (0..7)

    // stage ENCODER weights
    stage_weights(sm, tid, enc_w_hh + c * (G3 * HH), enc_w_ih + c * (G3 * 2), 2,
                  enc_b_ih + c * G3, enc_b_hh + c * G3);
    __syncthreads();

    const int seqa = (blockIdx.x * NT + tid) * 2;   // this thread: seqs (seqa, seqa+1)
    float2* hs = (float2*)(sm + OFF_HS);

    // prefetch decoder seed values early (hide DRAM latency under encoder)
    float lva = X[(size_t)seqa * (TT * 2) + 22];          // X[seq, t=11, f=0]
    float lvb = X[(size_t)(seqa + 1) * (TT * 2) + 22];

    float ha[HH], hb[HH];
    #pragma unroll
    for (int k = 0; k < HH; ++k) {
        ha[k] = 0.0f; hb[k] = 0.0f;
        hs[k * NT + tid] = make_float2(0.0f, 0.0f);   // own slots only, no sync needed
    }

    // ---- encoder ----
    const int s = c + 3;
    const float2* hvp = (const float2*)g_hv;
    for (int st = 0; st < s; ++st) {
        float4 xv = *(const float4*)(hvp + (size_t)(c * TOUT + st) * BN + seqa);
        gru_step2<true>(ha, hb, sm, tid, wrot, xv.x, xv.y, xv.z, xv.w);
    }

    // restage DECODER weights over the same buffer
    __syncthreads();
    stage_weights(sm, tid, dec_w_hh + c * (G3 * HH), dec_w_ih + c * G3, 1,
                  dec_b_ih + c * G3, dec_b_hh + c * G3);
    if (tid < HH)  sm[OFF_L1W + tid] = lin1_w[c * HH + tid];
    if (tid == HH) sm[OFF_L1B] = lin1_b[c];
    __syncthreads();

    // ---- decoder ----
    const float l1b = sm[OFF_L1B];
    for (int st = 0; st < TOUT; ++st) {
        gru_step2<false>(ha, hb, sm, tid, wrot, lva, 0.0f, lvb, 0.0f);
        float va = l1b, vb = l1b;
        #pragma unroll
        for (int k = 0; k < HH; ++k) {
            float w = sm[OFF_L1W + k];
            va = fmaf(ha[k], w, va);
            vb = fmaf(hb[k], w, vb);
        }
        *(float2*)&g_vals[(size_t)(c * TOUT + st) * BN + seqa] = make_float2(va, vb);
        lva = va; lvb = vb;
    }
}

// precompute encoder inputs hv[c][st][seq] = (x0,x1)
__global__ void __launch_bounds__(256) krnn_hv(
    const float* __restrict__ X,
    const float* __restrict__ lin2_w, const float* __restrict__ lin2_b)
{
    const int seq = blockIdx.x * 256 + threadIdx.x;
    float Xl[24];
    {
        const float4* xp = (const float4*)(X + (size_t)seq * (TT * 2));
        #pragma unroll
        for (int q = 0; q < 6; ++q) {
            float4 v = xp[q];
            Xl[4*q+0] = v.x; Xl[4*q+1] = v.y; Xl[4*q+2] = v.z; Xl[4*q+3] = v.w;
        }
    }
    float2* hvp = (float2*)g_hv;
    for (int c = 0; c < CC; ++c) {
        const int s = c + 3;
        for (int st = 0; st < s; ++st) {
            float b = lin2_b[c * 12 + st];
            float x0 = b, x1 = b;
            #pragma unroll
            for (int t = 0; t < TT; ++t) {
                float w = lin2_w[c * 144 + st * 12 + t];
                x0 = fmaf(Xl[2 * t],     w, x0);
                x1 = fmaf(Xl[2 * t + 1], w, x1);
            }
            hvp[(size_t)(c * TOUT + st) * BN + seq] = make_float2(x0, x1);
        }
    }
}

__global__ void __launch_bounds__(256) krnn_combine(
    const float* __restrict__ X,
    const float* __restrict__ embed1,
    float* __restrict__ out)
{
    const int seq = blockIdx.x * 256 + threadIdx.x;

    float q[TT];
    #pragma unroll
    for (int t = 0; t < TT; ++t) q[t] = X[(size_t)seq * (TT * 2) + t * 2];

    float wq[TOUT];
    #pragma unroll
    for (int o = 0; o < TOUT; ++o) {
        float a = 0.0f;
        #pragma unroll
        for (int t = 0; t < TT; ++t) a = fmaf(q[t], embed1[t * TOUT + o], a);
        wq[o] = a;
    }

    float ov[TOUT * CC];
    #pragma unroll
    for (int cc = 0; cc < CC; ++cc)
        #pragma unroll
        for (int o = 0; o < TOUT; ++o)
            ov[o * CC + cc] = g_vals[((size_t)cc * TOUT + o) * BN + seq];

    float wc[CC];
    #pragma unroll
    for (int cc = 0; cc < CC; ++cc) {
        float a = 0.0f;
        #pragma unroll
        for (int o = 0; o < TOUT; ++o) a = fmaf(wq[o], ov[o * CC + cc], a);
        wc[cc] = a;
    }

    float m = wc[0];
    #pragma unroll
    for (int cc = 1; cc < CC; ++cc) m = fmaxf(m, wc[cc]);
    float e[CC]; float ssum = 0.0f;
    #pragma unroll
    for (int cc = 0; cc < CC; ++cc) { e[cc] = expf(wc[cc] - m); ssum += e[cc]; }
    float inv = 1.0f / ssum;

    #pragma unroll
    for (int o = 0; o < TOUT; ++o) {
        float a = 0.0f;
        #pragma unroll
        for (int cc = 0; cc < CC; ++cc) a = fmaf(ov[o * CC + cc], e[cc], a);
        out[(size_t)seq * TOUT + o] = a * inv;
    }
}

extern "C" void kernel_launch(void* const* d_in, const int* in_sizes, int n_in,
                              void* d_out, int out_size)
{
    // input order: A, X, enc_w_ih, enc_w_hh, enc_b_ih, enc_b_hh,
    //              dec_w_ih, dec_w_hh, dec_b_ih, dec_b_hh,
    //              lin1_w, lin1_b, lin2_w, lin2_b, embed1
    const float* X        = (const float*)d_in[1];
    const float* enc_w_ih = (const float*)d_in[2];
    const float* enc_w_hh = (const float*)d_in[3];
    const float* enc_b_ih = (const float*)d_in[4];
    const float* enc_b_hh = (const float*)d_in[5];
    const float* dec_w_ih = (const float*)d_in[6];
    const float* dec_w_hh = (const float*)d_in[7];
    const float* dec_b_ih = (const float*)d_in[8];
    const float* dec_b_hh = (const float*)d_in[9];
    const float* lin1_w   = (const float*)d_in[10];
    const float* lin1_b   = (const float*)d_in[11];
    const float* lin2_w   = (const float*)d_in[12];
    const float* lin2_b   = (const float*)d_in[13];
    const float* embed1   = (const float*)d_in[14];

    cudaFuncSetAttribute(krnn_main, cudaFuncAttributeMaxDynamicSharedMemorySize, SMEM_BYTES);

    krnn_hv<<<BN / 256, 256>>>(X, lin2_w, lin2_b);

    dim3 grid(BN / (NT * 2), CC);
    krnn_main<<<grid, NT, SMEM_BYTES>>>(
        X, enc_w_ih, enc_w_hh, enc_b_ih, enc_b_hh,
        dec_w_ih, dec_w_hh, dec_b_ih, dec_b_hh,
        lin1_w, lin1_b);

    krnn_combine<<<BN / 256, 256>>>(X, embed1, (float*)d_out);
}